// round 6
// baseline (speedup 1.0000x reference)
#include <cuda_runtime.h>
#include <cuda_fp16.h>

#define N_NODES 10000
#define D_FEAT  128
#define BATCH   8192
#define K_NEIGH 25

// fp16 scratch copy of feat: 10000*128*2B = 2.56 MB (static device scratch).
__device__ __half2 g_feat_h[N_NODES * D_FEAT / 2];

__global__ void __launch_bounds__(256) convert_feat_kernel(
    const float* __restrict__ feat)
{
    const int i = blockIdx.x * blockDim.x + threadIdx.x;   // over float2 pairs
    if (i < N_NODES * D_FEAT / 2) {
        const float2 v = ((const float2*)feat)[i];
        g_feat_h[i] = __floats2half2_rn(v.x, v.y);
    }
}

__global__ void __launch_bounds__(256) mean_agg_kernel(
    const int*   __restrict__ nodes,      // [BATCH]           (int32)
    const int*   __restrict__ neigh_idx,  // [BATCH, K]        (int32)
    const float* __restrict__ adj,        // [N_NODES, N_NODES]
    const float* __restrict__ fsim,       // [N_NODES, N_NODES]
    float*       __restrict__ out)        // [BATCH, D_FEAT]
{
    const int warp = (blockIdx.x * blockDim.x + threadIdx.x) >> 5;
    const int lane = threadIdx.x & 31;
    if (warp >= BATCH) return;

    const int row = nodes[warp];

    // Lanes 0..24 each gather one neighbor weight (fp32, exact).
    int   my_idx = 0;
    float my_w   = 0.0f;
    if (lane < K_NEIGH) {
        my_idx = neigh_idx[warp * K_NEIGH + lane];
        const unsigned base = (unsigned)row * N_NODES + (unsigned)my_idx;
        my_w = adj[base] + fsim[base];
    }

    // denom = sum of weights (lanes >= 25 hold 0)
    float denom = my_w;
    #pragma unroll
    for (int off = 16; off; off >>= 1)
        denom += __shfl_xor_sync(0xffffffffu, denom, off);

    // Weighted feature accumulation (feat in fp16, accumulate in fp32).
    // Each lane owns 4 contiguous dims = 2 half2 = one 8B load.
    // A full fp16 row = 128 halves = 256B = 32 uint2 -> stride D_FEAT/4.
    const uint2* __restrict__ fh = ((const uint2*)g_feat_h) + lane;

    float2 accA = make_float2(0.f, 0.f);   // dims 4*lane+0,1
    float2 accB = make_float2(0.f, 0.f);   // dims 4*lane+2,3

    #pragma unroll
    for (int k = 0; k < K_NEIGH; k++) {
        const float wk = __shfl_sync(0xffffffffu, my_w, k);
        const int   ik = __shfl_sync(0xffffffffu, my_idx, k);
        const uint2 raw = fh[(unsigned)ik * (D_FEAT / 4)];
        const float2 fA = __half22float2(*(const __half2*)&raw.x);
        const float2 fB = __half22float2(*(const __half2*)&raw.y);
        accA.x += wk * fA.x;
        accA.y += wk * fA.y;
        accB.x += wk * fB.x;
        accB.y += wk * fB.y;
    }

    const float inv = 1.0f / denom;
    float4 o;
    o.x = accA.x * inv;
    o.y = accA.y * inv;
    o.z = accB.x * inv;
    o.w = accB.y * inv;
    ((float4*)out)[warp * (D_FEAT / 4) + lane] = o;
}

extern "C" void kernel_launch(void* const* d_in, const int* in_sizes, int n_in,
                              void* d_out, int out_size)
{
    const int*   nodes = (const int*)d_in[0];
    const int*   neigh = (const int*)d_in[1];
    const float* feat  = (const float*)d_in[2];
    const float* adj   = (const float*)d_in[3];
    const float* fsim  = (const float*)d_in[4];
    float*       out   = (float*)d_out;

    // Kernel 1: convert feat to fp16 scratch (same stream -> ordered).
    const int conv_elems  = N_NODES * D_FEAT / 2;
    const int conv_blocks = (conv_elems + 255) / 256;
    convert_feat_kernel<<<conv_blocks, 256>>>(feat);

    // Kernel 2: weighted mean aggregation.
    const int threads = 256;                                   // 8 warps/block
    const int blocks  = (BATCH * 32 + threads - 1) / threads;  // 1024 blocks
    mean_agg_kernel<<<blocks, threads>>>(nodes, neigh, adj, fsim, out);
}